// round 1
// baseline (speedup 1.0000x reference)
#include <cuda_runtime.h>
#include <math.h>

// Problem constants
#define BSZ 4
#define SEQ 2048
#define DIM 2048
#define NST 16
#define RNK 512
#define MROWS (BSZ * SEQ)      // 8192
#define NW    (RNK + NST)      // 528 real output cols of fused GEMM
#define NP    576              // padded to multiple of 64

// ---- scratch (static device memory; no runtime allocation) ----
__device__ float g_w[NP * DIM];            // packed [dt_w^T | B | 0], row-major (NP x DIM)
__device__ float g_out1[MROWS * NP];       // delta1 (cols 0..511) and xB (cols 512..527)
__device__ float g_abar[MROWS * NST];      // exp(delta * A), layout (b*S+s, n)
__device__ float g_xb[MROWS * NST];        // xB compact
__device__ float g_hs[MROWS * NST];        // scan states

// ============================================================
// K0: pack weights: rows 0..511 = dt_w[r][:], rows 512..527 = B[:,n], rest 0
// ============================================================
__global__ void pack_w_kernel(const float* __restrict__ dt_w,
                              const float* __restrict__ Bm) {
    int idx = blockIdx.x * blockDim.x + threadIdx.x;
    if (idx >= NP * DIM) return;
    int j = idx / DIM;
    int k = idx - j * DIM;
    float v = 0.0f;
    if (j < RNK)            v = dt_w[j * DIM + k];
    else if (j < RNK + NST) v = Bm[k * NST + (j - RNK)];
    g_w[idx] = v;
}

// ============================================================
// K1: fp32 GEMM  g_out1[m][j] = sum_k x[m][k] * g_w[j][k]
// Tiles: BM=128, BN=64, BK=16, 256 threads, 8x4 per thread
// ============================================================
#define BM 128
#define BN 64
#define BK 16

__global__ void __launch_bounds__(256) gemm_kernel(const float* __restrict__ x) {
    __shared__ float As[BK][BM];   // 8KB
    __shared__ float Bs[BK][BN];   // 4KB

    int tid = threadIdx.x;
    int bm = blockIdx.x * BM;
    int bn = blockIdx.y * BN;
    int tx = tid & 15;         // 0..15 -> col group of 4
    int ty = tid >> 4;         // 0..15 -> row group of 8

    float acc[8][4] = {};

    for (int kt = 0; kt < DIM / BK; kt++) {
        // Load A tile: 128x16 floats = 512 float4, 2 per thread
        #pragma unroll
        for (int t = 0; t < 2; t++) {
            int l = tid + t * 256;
            int row = l >> 2;
            int c4 = (l & 3) * 4;
            float4 v = *(const float4*)&x[(size_t)(bm + row) * DIM + kt * BK + c4];
            As[c4 + 0][row] = v.x;
            As[c4 + 1][row] = v.y;
            As[c4 + 2][row] = v.z;
            As[c4 + 3][row] = v.w;
        }
        // Load B tile: 64x16 floats = 256 float4, 1 per thread
        {
            int row = tid >> 2;
            int c4 = (tid & 3) * 4;
            float4 v = *(const float4*)&g_w[(size_t)(bn + row) * DIM + kt * BK + c4];
            Bs[c4 + 0][row] = v.x;
            Bs[c4 + 1][row] = v.y;
            Bs[c4 + 2][row] = v.z;
            Bs[c4 + 3][row] = v.w;
        }
        __syncthreads();

        #pragma unroll
        for (int k = 0; k < BK; k++) {
            float ra[8], rb[4];
            *(float4*)&ra[0] = *(const float4*)&As[k][ty * 8];
            *(float4*)&ra[4] = *(const float4*)&As[k][ty * 8 + 4];
            *(float4*)&rb[0] = *(const float4*)&Bs[k][tx * 4];
            #pragma unroll
            for (int i = 0; i < 8; i++)
                #pragma unroll
                for (int j = 0; j < 4; j++)
                    acc[i][j] += ra[i] * rb[j];
        }
        __syncthreads();
    }

    #pragma unroll
    for (int i = 0; i < 8; i++) {
        float4 v = make_float4(acc[i][0], acc[i][1], acc[i][2], acc[i][3]);
        *(float4*)&g_out1[(size_t)(bm + ty * 8 + i) * NP + bn + tx * 4] = v;
    }
}

// ============================================================
// K1b: delta = (delta1 + dt_b) @ dt_pw -> sigmoid -> A_bar = exp(delta*A)
// Block: 256 threads = 16 rows x 16 n.  dt_pw transposed in smem (pad 514).
// ============================================================
#define PW_STRIDE 514

__global__ void __launch_bounds__(256) delta_kernel(const float* __restrict__ A_log,
                                                    const float* __restrict__ dt_b,
                                                    const float* __restrict__ dt_pw) {
    __shared__ float s_pw[NST * PW_STRIDE];  // [n][r], padded
    __shared__ float s_db[RNK];

    int tid = threadIdx.x;
    for (int i = tid; i < RNK * NST; i += 256) {
        int r = i >> 4;
        int n = i & 15;
        s_pw[n * PW_STRIDE + r] = dt_pw[i];  // dt_pw[r][n]
    }
    for (int i = tid; i < RNK; i += 256) s_db[i] = dt_b[i];
    __syncthreads();

    int rr = tid >> 4;                 // 0..15
    int n  = tid & 15;                 // 0..15
    int m  = blockIdx.x * 16 + rr;

    const float* row = &g_out1[(size_t)m * NP];
    const float* pw  = &s_pw[n * PW_STRIDE];

    float acc = 0.0f;
    #pragma unroll 8
    for (int r = 0; r < RNK; r++) {
        acc += (row[r] + s_db[r]) * pw[r];
    }

    float sig   = 1.0f / (1.0f + expf(-acc));
    float delta = 0.001f + 0.099f * sig;
    float A     = expf(A_log[n]);
    float abar  = expf(delta * A);

    g_abar[m * NST + n] = abar;
    g_xb[m * NST + n]   = row[RNK + n];
}

// ============================================================
// K2: parallel scan per channel (b,n). 64 blocks, 256 threads, chunk 8.
//     h_s = a_s * h_{s-1} + xb_s
// ============================================================
#define CHUNK 8

__global__ void __launch_bounds__(256) scan_kernel(void) {
    int ch = blockIdx.x;           // 0..63
    int b  = ch >> 4;
    int n  = ch & 15;
    int t  = threadIdx.x;          // 0..255
    int s0 = t * CHUNK;
    int base = (b * SEQ) * NST + n;

    float a[CHUNK], xb[CHUNK];
    #pragma unroll
    for (int i = 0; i < CHUNK; i++) {
        a[i]  = g_abar[base + (s0 + i) * NST];
        xb[i] = g_xb[base + (s0 + i) * NST];
    }

    float ap = 1.0f, h = 0.0f;
    #pragma unroll
    for (int i = 0; i < CHUNK; i++) {
        h = a[i] * h + xb[i];
        ap *= a[i];
    }

    __shared__ float sa[256], sh[256];
    sa[t] = ap;
    sh[t] = h;
    __syncthreads();

    // Hillis-Steele inclusive scan with operator:
    // prefix P then chunk C: a = aP*aC, h = aC*hP + hC
    for (int off = 1; off < 256; off <<= 1) {
        float ca = sa[t], chh = sh[t];
        float pa = 1.0f, ph = 0.0f;
        if (t >= off) { pa = sa[t - off]; ph = sh[t - off]; }
        __syncthreads();
        if (t >= off) {
            sa[t] = pa * ca;
            sh[t] = ca * ph + chh;
        }
        __syncthreads();
    }

    float hin = (t > 0) ? sh[t - 1] : 0.0f;
    #pragma unroll
    for (int i = 0; i < CHUNK; i++) {
        hin = a[i] * hin + xb[i];
        g_hs[base + (s0 + i) * NST] = hin;
    }
}

// ============================================================
// K3: y[m][d] = sum_n hs[m][n] * C[n][d].  128 rows x 128 cols per block.
// ============================================================
__global__ void __launch_bounds__(128) proj_kernel(const float* __restrict__ Cm,
                                                   float* __restrict__ y) {
    __shared__ float shs[128][NST];   // 8KB
    int mt = blockIdx.x * 128;
    int d0 = blockIdx.y * 128;
    int tid = threadIdx.x;

    for (int i = tid; i < 128 * NST; i += 128) {
        shs[i >> 4][i & 15] = g_hs[(size_t)mt * NST + i];
    }
    float c[NST];
    #pragma unroll
    for (int n = 0; n < NST; n++) c[n] = Cm[n * DIM + d0 + tid];
    __syncthreads();

    for (int m = 0; m < 128; m++) {
        float acc = 0.0f;
        #pragma unroll
        for (int n = 0; n < NST; n++) acc += shs[m][n] * c[n];
        y[(size_t)(mt + m) * DIM + d0 + tid] = acc;
    }
}

// ============================================================
// launch
// ============================================================
extern "C" void kernel_launch(void* const* d_in, const int* in_sizes, int n_in,
                              void* d_out, int out_size) {
    const float* x     = (const float*)d_in[0];
    const float* A_log = (const float*)d_in[1];
    const float* Bm    = (const float*)d_in[2];
    const float* Cm    = (const float*)d_in[3];
    const float* dt_w  = (const float*)d_in[4];
    const float* dt_b  = (const float*)d_in[5];
    const float* dt_pw = (const float*)d_in[6];
    float* y = (float*)d_out;

    pack_w_kernel<<<(NP * DIM + 255) / 256, 256>>>(dt_w, Bm);
    gemm_kernel<<<dim3(MROWS / BM, NP / BN), 256>>>(x);
    delta_kernel<<<MROWS / 16, 256>>>(A_log, dt_b, dt_pw);
    scan_kernel<<<BSZ * NST, 256>>>();
    proj_kernel<<<dim3(MROWS / 128, DIM / 128), 128>>>(Cm, y);
}

// round 4
// speedup vs baseline: 3.9385x; 3.9385x over previous
#include <cuda_runtime.h>
#include <math.h>
#include <stdint.h>

// Problem constants
#define BSZ 4
#define SEQ 2048
#define DIM 2048
#define NST 16
#define RNK 512
#define MROWS (BSZ * SEQ)      // 8192
#define NC    32               // fused output cols: 16 delta_pre + 16 xB

// ---- scratch (static device memory) ----
__device__ float g_w32[DIM * NC];     // [d][0..15]=W2, [d][16..31]=B
__device__ float g_bias[NST];         // dt_b @ dt_pw
__device__ float g_An[NST];           // exp(A_log)
__device__ float g_abar[MROWS * NST];
__device__ float g_xb[MROWS * NST];
__device__ float g_hs[MROWS * NST];

__device__ __forceinline__ uint32_t smem_u32(const void* p) {
    uint32_t a;
    asm("{ .reg .u64 t; cvta.to.shared.u64 t, %1; cvt.u32.u64 %0, t; }" : "=r"(a) : "l"(p));
    return a;
}
__device__ __forceinline__ void cp16(uint32_t dst, const float* src) {
    asm volatile("cp.async.cg.shared.global [%0], [%1], 16;" :: "r"(dst), "l"(src));
}

// ============================================================
// P0: W2[d][n] = sum_r dt_w[r][d] * dt_pw[r][n]   (d-coalesced reads)
// 32768 threads: idx = n*2048 + d
// ============================================================
__global__ void __launch_bounds__(256) prep_w2_kernel(const float* __restrict__ dt_w,
                                                      const float* __restrict__ dt_pw) {
    int idx = blockIdx.x * blockDim.x + threadIdx.x;
    int n = idx >> 11;          // 0..15
    int d = idx & 2047;
    float a0 = 0.f, a1 = 0.f, a2 = 0.f, a3 = 0.f;
    #pragma unroll 2
    for (int r = 0; r < RNK; r += 4) {
        a0 += dt_w[(r + 0) * DIM + d] * dt_pw[(r + 0) * NST + n];
        a1 += dt_w[(r + 1) * DIM + d] * dt_pw[(r + 1) * NST + n];
        a2 += dt_w[(r + 2) * DIM + d] * dt_pw[(r + 2) * NST + n];
        a3 += dt_w[(r + 3) * DIM + d] * dt_pw[(r + 3) * NST + n];
    }
    g_w32[d * NC + n] = (a0 + a1) + (a2 + a3);
}

// P0b: copy B into cols 16..31 of g_w32
__global__ void __launch_bounds__(256) prep_b_kernel(const float* __restrict__ Bm) {
    int idx = blockIdx.x * blockDim.x + threadIdx.x;   // 32768
    int d = idx >> 4;
    int n = idx & 15;
    g_w32[d * NC + NST + n] = Bm[d * NST + n];
}

// P0c: bias_n = sum_r dt_b[r]*dt_pw[r][n];  An = exp(A_log)
__global__ void prep_small_kernel(const float* __restrict__ A_log,
                                  const float* __restrict__ dt_b,
                                  const float* __restrict__ dt_pw) {
    int t = threadIdx.x;
    if (t < NST) {
        float s = 0.0f;
        for (int r = 0; r < RNK; r++) s += dt_b[r] * dt_pw[r * NST + t];
        g_bias[t] = s;
        g_An[t]   = expf(A_log[t]);
    }
}

// ============================================================
// K1: fused GEMM + nonlinearity (static smem, cp.async double buffer)
//   acc[m][n] = sum_k x[m][k] * g_w32[k][n]
//   n<16 : abar = exp((0.001+0.099*sigmoid(acc+bias_n)) * An)
//   n>=16: xb = acc
// ============================================================
#define GBM 64
#define GBK 32
#define GNIT (DIM / GBK)       // 64
#define XROW 36                // 144B row pitch (16B aligned)

__global__ void __launch_bounds__(256) gemm_fused_kernel(const float* __restrict__ x) {
    __shared__ float sx[2][GBM][XROW];   // 18432 B
    __shared__ float sw[2][GBK][NC];     //  8192 B

    int tid = threadIdx.x;
    int bm  = blockIdx.x * GBM;
    int r0  = (tid >> 3) * 2;        // 0..62
    int c   = (tid & 7) * 4;         // 0..28

    const float* gx = x + (size_t)bm * DIM;

    // prefetch tile 0 -> buffer 0
    {
        #pragma unroll
        for (int t = 0; t < 2; t++) {
            int o = tid + t * 256; int row = o >> 3; int c4 = o & 7;
            cp16(smem_u32(&sx[0][row][c4 * 4]), gx + (size_t)row * DIM + c4 * 4);
        }
        {
            int row = tid >> 3; int c4 = tid & 7;
            cp16(smem_u32(&sw[0][row][c4 * 4]), g_w32 + row * NC + c4 * 4);
        }
        asm volatile("cp.async.commit_group;" ::: "memory");
    }

    float acc[2][4] = {};

    for (int it = 0; it < GNIT; it++) {
        int buf = it & 1;
        if (it + 1 < GNIT) {
            int nb = buf ^ 1;
            const float* gxx = gx + (it + 1) * GBK;
            const float* gww = g_w32 + (size_t)(it + 1) * GBK * NC;
            #pragma unroll
            for (int t = 0; t < 2; t++) {
                int o = tid + t * 256; int row = o >> 3; int c4 = o & 7;
                cp16(smem_u32(&sx[nb][row][c4 * 4]), gxx + (size_t)row * DIM + c4 * 4);
            }
            {
                int row = tid >> 3; int c4 = tid & 7;
                cp16(smem_u32(&sw[nb][row][c4 * 4]), gww + row * NC + c4 * 4);
            }
            asm volatile("cp.async.commit_group;" ::: "memory");
            asm volatile("cp.async.wait_group 1;" ::: "memory");
        } else {
            asm volatile("cp.async.wait_group 0;" ::: "memory");
        }
        __syncthreads();

        #pragma unroll
        for (int k4 = 0; k4 < GBK / 4; k4++) {
            float xa[4], xb[4];
            *(float4*)xa = *(const float4*)&sx[buf][r0][k4 * 4];
            *(float4*)xb = *(const float4*)&sx[buf][r0 + 1][k4 * 4];
            #pragma unroll
            for (int kk = 0; kk < 4; kk++) {
                float wr[4];
                *(float4*)wr = *(const float4*)&sw[buf][k4 * 4 + kk][c];
                #pragma unroll
                for (int j = 0; j < 4; j++) {
                    acc[0][j] += xa[kk] * wr[j];
                    acc[1][j] += xb[kk] * wr[j];
                }
            }
        }
        __syncthreads();
    }

    // fused epilogue
    #pragma unroll
    for (int i = 0; i < 2; i++) {
        int m = bm + r0 + i;
        #pragma unroll
        for (int j = 0; j < 4; j++) {
            int n = c + j;
            if (n < NST) {
                float v   = acc[i][j] + g_bias[n];
                float sig = 1.0f / (1.0f + expf(-v));
                float dl  = 0.001f + 0.099f * sig;
                g_abar[m * NST + n] = expf(dl * g_An[n]);
            } else {
                g_xb[m * NST + (n - NST)] = acc[i][j];
            }
        }
    }
}

// ============================================================
// K2: parallel scan per channel (b,n)
// ============================================================
#define CHUNK 8

__global__ void __launch_bounds__(256) scan_kernel(void) {
    int ch = blockIdx.x;
    int b  = ch >> 4;
    int n  = ch & 15;
    int t  = threadIdx.x;
    int s0 = t * CHUNK;
    int base = (b * SEQ) * NST + n;

    float a[CHUNK], xb[CHUNK];
    #pragma unroll
    for (int i = 0; i < CHUNK; i++) {
        a[i]  = g_abar[base + (s0 + i) * NST];
        xb[i] = g_xb[base + (s0 + i) * NST];
    }

    float ap = 1.0f, h = 0.0f;
    #pragma unroll
    for (int i = 0; i < CHUNK; i++) {
        h = a[i] * h + xb[i];
        ap *= a[i];
    }

    __shared__ float sa[256], sh[256];
    sa[t] = ap;
    sh[t] = h;
    __syncthreads();

    for (int off = 1; off < 256; off <<= 1) {
        float ca = sa[t], chh = sh[t];
        float pa = 1.0f, ph = 0.0f;
        if (t >= off) { pa = sa[t - off]; ph = sh[t - off]; }
        __syncthreads();
        if (t >= off) {
            sa[t] = pa * ca;
            sh[t] = ca * ph + chh;
        }
        __syncthreads();
    }

    float hin = (t > 0) ? sh[t - 1] : 0.0f;
    #pragma unroll
    for (int i = 0; i < CHUNK; i++) {
        hin = a[i] * hin + xb[i];
        g_hs[base + (s0 + i) * NST] = hin;
    }
}

// ============================================================
// K3: y[m][d] = sum_n hs[m][n] * C[n][d]
// ============================================================
__global__ void __launch_bounds__(128) proj_kernel(const float* __restrict__ Cm,
                                                   float* __restrict__ y) {
    __shared__ float shs[128][NST];
    int mt = blockIdx.x * 128;
    int d0 = blockIdx.y * 128;
    int tid = threadIdx.x;

    for (int i = tid; i < 128 * NST; i += 128) {
        shs[i >> 4][i & 15] = g_hs[(size_t)mt * NST + i];
    }
    float cc[NST];
    #pragma unroll
    for (int n = 0; n < NST; n++) cc[n] = Cm[n * DIM + d0 + tid];
    __syncthreads();

    for (int m = 0; m < 128; m++) {
        float acc = 0.0f;
        #pragma unroll
        for (int n = 0; n < NST; n++) acc += shs[m][n] * cc[n];
        y[(size_t)(mt + m) * DIM + d0 + tid] = acc;
    }
}

// ============================================================
// launch  (graph-capturable: kernel launches only)
// ============================================================
extern "C" void kernel_launch(void* const* d_in, const int* in_sizes, int n_in,
                              void* d_out, int out_size) {
    const float* x     = (const float*)d_in[0];
    const float* A_log = (const float*)d_in[1];
    const float* Bm    = (const float*)d_in[2];
    const float* Cm    = (const float*)d_in[3];
    const float* dt_w  = (const float*)d_in[4];
    const float* dt_b  = (const float*)d_in[5];
    const float* dt_pw = (const float*)d_in[6];
    float* y = (float*)d_out;

    prep_w2_kernel<<<(NST * DIM) / 256, 256>>>(dt_w, dt_pw);
    prep_b_kernel<<<(NST * DIM) / 256, 256>>>(Bm);
    prep_small_kernel<<<1, 32>>>(A_log, dt_b, dt_pw);
    gemm_fused_kernel<<<MROWS / GBM, 256>>>(x);
    scan_kernel<<<BSZ * NST, 256>>>();
    proj_kernel<<<dim3(MROWS / 128, DIM / 128), 128>>>(Cm, y);
}